// round 1
// baseline (speedup 1.0000x reference)
#include <cuda_runtime.h>

#define BB 2
#define FIN 128
#define NN 192
#define SS 192
#define HH 4
#define DD 64
#define CC 256          // H*D
#define NEG 0.2f
#define TOTF 73728.0f   // B*S*N

// ---------------- scratch (device globals; no allocation) ----------------
__device__ float d_u[2][HH][FIN];        // [0]=u_src, [1]=u_dst
__device__ float d_c[2][HH];             // bias dots
__device__ float d_sumxp[BB][FIN];       // partial sums of X per (b,f)
__device__ float d_sumg[CC];             // sum_g flattened (h*64+d)
__device__ float d_Ssrc[BB][HH][NN][SS]; // src[b,h,n,s]
__device__ float d_Sdst[BB][HH][SS][NN]; // dst[b,h,s,m]
__device__ float d_SdstT[BB][HH][NN][SS];// dst transposed [b,h,m,s]
__device__ float d_denom[BB][HH][NN][NN];// denom[b,h,n,m]
__device__ float d_alph[BB][HH][NN][SS]; // alph_sum[b,h,n,s]

// ---------------- K0: u vectors + bias constants ----------------
__global__ void k_prep(const float* __restrict__ W_lin,
                       const float* __restrict__ b_lin,
                       const float* __restrict__ W_attn) {
    int f = threadIdx.x;  // 128 threads
    #pragma unroll
    for (int h = 0; h < HH; h++) {
        float as = 0.f, ad = 0.f;
        #pragma unroll 8
        for (int d = 0; d < DD; d++) {
            float w = W_lin[f * CC + h * DD + d];
            as += w * W_attn[d];
            ad += w * W_attn[DD + d];
        }
        d_u[0][h][f] = as;
        d_u[1][h][f] = ad;
    }
    if (f < HH) {
        int h = f;
        float cs = 0.f, cd = 0.f;
        for (int d = 0; d < DD; d++) {
            cs += b_lin[h * DD + d] * W_attn[d];
            cd += b_lin[h * DD + d] * W_attn[DD + d];
        }
        d_c[0][h] = cs;
        d_c[1][h] = cd;
    }
}

// ---------------- K1: partial sums of X over (n,s) per (b,f) ----------------
__global__ void k_sumx(const float* __restrict__ X) {
    int bf = blockIdx.x;  // b*128+f, 256 blocks
    const float* p = X + (size_t)bf * (NN * SS);
    float acc = 0.f;
    for (int i = threadIdx.x; i < NN * SS; i += 256) acc += p[i];
    __shared__ float sm[256];
    sm[threadIdx.x] = acc;
    __syncthreads();
    #pragma unroll
    for (int st = 128; st > 0; st >>= 1) {
        if (threadIdx.x < st) sm[threadIdx.x] += sm[threadIdx.x + st];
        __syncthreads();
    }
    if (threadIdx.x == 0) d_sumxp[bf / FIN][bf % FIN] = sm[0];
}

// ---------------- K2: sum_g ----------------
__global__ void k_sumg(const float* __restrict__ W_lin,
                       const float* __restrict__ b_lin) {
    int c = threadIdx.x;  // 256 threads, 1 block
    float acc = 0.f;
    #pragma unroll 8
    for (int f = 0; f < FIN; f++)
        acc += (d_sumxp[0][f] + d_sumxp[1][f]) * W_lin[f * CC + c];
    d_sumg[c] = acc + TOTF * b_lin[c];
}

// ---------------- K3: src/dst projections ----------------
// grid (48, BB), block 192 (=s). Each thread does 4 n-positions.
__global__ void k_proj(const float* __restrict__ X) {
    __shared__ float su[2][HH][FIN];
    int tid = threadIdx.x;
    for (int i = tid; i < 2 * HH * FIN; i += 192)
        ((float*)su)[i] = ((const float*)d_u)[i];
    __syncthreads();

    int b = blockIdx.y;
    int n0 = blockIdx.x;  // n = n0, n0+48, n0+96, n0+144
    int s = tid;
    float as[4][HH], ad[4][HH];
    #pragma unroll
    for (int j = 0; j < 4; j++)
        #pragma unroll
        for (int h = 0; h < HH; h++) { as[j][h] = 0.f; ad[j][h] = 0.f; }

    const float* Xb = X + (size_t)b * FIN * NN * SS;
    #pragma unroll 4
    for (int f = 0; f < FIN; f++) {
        float x0 = Xb[(f * NN + n0      ) * SS + s];
        float x1 = Xb[(f * NN + n0 +  48) * SS + s];
        float x2 = Xb[(f * NN + n0 +  96) * SS + s];
        float x3 = Xb[(f * NN + n0 + 144) * SS + s];
        #pragma unroll
        for (int h = 0; h < HH; h++) {
            float wu = su[0][h][f], wd = su[1][h][f];
            as[0][h] += x0 * wu;  ad[0][h] += x0 * wd;
            as[1][h] += x1 * wu;  ad[1][h] += x1 * wd;
            as[2][h] += x2 * wu;  ad[2][h] += x2 * wd;
            as[3][h] += x3 * wu;  ad[3][h] += x3 * wd;
        }
    }
    #pragma unroll
    for (int j = 0; j < 4; j++) {
        int n = n0 + j * 48;
        #pragma unroll
        for (int h = 0; h < HH; h++) {
            float sv = as[j][h] + d_c[0][h];
            float dv = ad[j][h] + d_c[1][h];
            d_Ssrc[b][h][n][s]  = sv;  // coalesced in s
            d_Sdst[b][h][s][n]  = dv;  // strided (one-time cost)
            d_SdstT[b][h][n][s] = dv;  // coalesced in s
        }
    }
}

// ---------------- K4: denom[b,h,n,m] = sum_s mask(s,n)*exp(lrelu(...)) ----------------
// grid (NN, HH, BB), block 192 (=m)
__global__ void k_denom(const int* __restrict__ A,
                        const float* __restrict__ b_attn) {
    int n = blockIdx.x, h = blockIdx.y, b = blockIdx.z;
    int m = threadIdx.x;
    __shared__ float ssv[SS];
    __shared__ int   smk[SS];
    ssv[m] = d_Ssrc[b][h][n][m];  // m reused as s-index for staging
    smk[m] = A[m * NN + n];
    __syncthreads();

    float cb = b_attn[0];
    float acc = 0.f;
    const float* dstp = &d_Sdst[b][h][0][m];
    for (int s = 0; s < SS; s++) {
        if (smk[s]) {  // warp-uniform branch
            float e = ssv[s] + dstp[s * NN] + cb;
            e = fmaxf(e, NEG * e);
            acc += __expf(e);
        }
    }
    d_denom[b][h][n][m] = acc;
}

// ---------------- K5: alph_sum[b,h,n,s] = mask * sum_m exp(...)/denom ----------------
// grid (NN, HH, BB), block 192 (=s)
__global__ void k_alph(const int* __restrict__ A,
                       const float* __restrict__ b_attn) {
    int n = blockIdx.x, h = blockIdx.y, b = blockIdx.z;
    int s = threadIdx.x;
    __shared__ float rden[NN];
    float dn = d_denom[b][h][n][s];  // s reused as m-index for staging
    rden[s] = 1.0f / dn;             // inf only if that (n) col fully masked -> unused
    __syncthreads();

    int mk = A[s * NN + n];
    float acc = 0.f;
    if (mk) {
        float cb = b_attn[0];
        float sv = d_Ssrc[b][h][n][s];
        const float* dtp = &d_SdstT[b][h][0][s];
        #pragma unroll 4
        for (int m = 0; m < NN; m++) {
            float e = sv + dtp[m * SS] + cb;  // coalesced across s
            e = fmaxf(e, NEG * e);
            acc += __expf(e) * rden[m];
        }
    }
    d_alph[b][h][n][s] = acc;
}

// ---------------- K6: out[b, h*64+d, n, s] = alph[b,h,n,s] * sum_g[h*64+d] ----------------
// float4 over s; grid 18432, block 256
__global__ void k_out(float* __restrict__ out) {
    int idx = blockIdx.x * 256 + threadIdx.x;  // float4 index, total 4718592
    int s4 = idx % 48;
    int n  = (idx / 48) % NN;
    int c  = (idx / (48 * NN)) % CC;
    int b  =  idx / (48 * NN * CC);
    int h  = c >> 6;
    float4 a = ((const float4*)&d_alph[b][h][n][0])[s4];
    float  g = d_sumg[c];
    float4 o = make_float4(a.x * g, a.y * g, a.z * g, a.w * g);
    ((float4*)out)[idx] = o;
}

extern "C" void kernel_launch(void* const* d_in, const int* in_sizes, int n_in,
                              void* d_out, int out_size) {
    const float* X      = (const float*)d_in[0];
    const int*   A      = (const int*)  d_in[1];
    const float* W_lin  = (const float*)d_in[2];
    const float* b_lin  = (const float*)d_in[3];
    const float* W_attn = (const float*)d_in[4];
    const float* b_attn = (const float*)d_in[5];
    float* out = (float*)d_out;

    k_prep<<<1, 128>>>(W_lin, b_lin, W_attn);
    k_sumx<<<BB * FIN, 256>>>(X);
    k_sumg<<<1, 256>>>(W_lin, b_lin);
    k_proj<<<dim3(48, BB), 192>>>(X);
    k_denom<<<dim3(NN, HH, BB), 192>>>(A, b_attn);
    k_alph<<<dim3(NN, HH, BB), 192>>>(A, b_attn);
    k_out<<<18432, 256>>>(out);
}

// round 2
// speedup vs baseline: 1.0578x; 1.0578x over previous
#include <cuda_runtime.h>

#define BB 2
#define FIN 128
#define NN 192
#define SS 192
#define HH 4
#define DD 64
#define CC 256          // H*D
#define NEG 0.2f
#define TOTF 73728.0f   // B*S*N
#define L2E 1.44269504088896f
#define CH 12           // n per attn block -> grid 16*4*2 = 128 blocks (1 wave)
#define PITCH 193       // smem slab pitch: bank(m*193+s) conflict-free both passes

// ---------------- scratch (device globals; no allocation) ----------------
__device__ float d_u[2][HH][FIN];        // [0]=u_src, [1]=u_dst
__device__ float d_c[2][HH];             // bias dots
__device__ float d_sumxp[BB][FIN];       // partial sums of X per (b,f)
__device__ float d_sumg[CC];             // sum_g flattened (h*64+d)
__device__ float d_Ssrc[BB][HH][NN][SS]; // (src+cb)*L2E  [n][s]
__device__ float d_Sdst[BB][HH][NN][SS]; // dst*L2E       [m][s]  (coalesced)
__device__ float d_alph[BB][HH][NN][SS]; // alpha row-sums

// ---------------- K0: u vectors + bias constants ----------------
__global__ void k_prep(const float* __restrict__ W_lin,
                       const float* __restrict__ b_lin,
                       const float* __restrict__ W_attn) {
    int f = threadIdx.x;  // 128 threads
    #pragma unroll
    for (int h = 0; h < HH; h++) {
        float as = 0.f, ad = 0.f;
        #pragma unroll 8
        for (int d = 0; d < DD; d++) {
            float w = W_lin[f * CC + h * DD + d];
            as += w * W_attn[d];
            ad += w * W_attn[DD + d];
        }
        d_u[0][h][f] = as;
        d_u[1][h][f] = ad;
    }
    if (f < HH) {
        int h = f;
        float cs = 0.f, cd = 0.f;
        for (int d = 0; d < DD; d++) {
            cs += b_lin[h * DD + d] * W_attn[d];
            cd += b_lin[h * DD + d] * W_attn[DD + d];
        }
        d_c[0][h] = cs;
        d_c[1][h] = cd;
    }
}

// ---------------- K1: partial sums of X over (n,s) per (b,f), float4 ----------------
__global__ void k_sumx(const float* __restrict__ X) {
    int bf = blockIdx.x;  // 256 blocks
    const float4* p = (const float4*)(X + (size_t)bf * (NN * SS));
    float acc = 0.f;
    for (int i = threadIdx.x; i < NN * SS / 4; i += 256) {
        float4 v = p[i];
        acc += (v.x + v.y) + (v.z + v.w);
    }
    __shared__ float sm[256];
    sm[threadIdx.x] = acc;
    __syncthreads();
    #pragma unroll
    for (int st = 128; st > 0; st >>= 1) {
        if (threadIdx.x < st) sm[threadIdx.x] += sm[threadIdx.x + st];
        __syncthreads();
    }
    if (threadIdx.x == 0) d_sumxp[bf / FIN][bf % FIN] = sm[0];
}

// ---------------- K2: sum_g ----------------
__global__ void k_sumg(const float* __restrict__ W_lin,
                       const float* __restrict__ b_lin) {
    int c = threadIdx.x;  // 256 threads, 1 block
    float acc = 0.f;
    #pragma unroll 8
    for (int f = 0; f < FIN; f++)
        acc += (d_sumxp[0][f] + d_sumxp[1][f]) * W_lin[f * CC + c];
    d_sumg[c] = acc + TOTF * b_lin[c];
}

// ---------------- K3: projections, 1 n per block ----------------
// grid (192, BB), block 192 (=s)
__global__ void __launch_bounds__(192) k_proj(const float* __restrict__ X,
                                              const float* __restrict__ b_attn) {
    __shared__ float su[2][HH][FIN];
    int tid = threadIdx.x;
    #pragma unroll
    for (int i = tid; i < 2 * HH * FIN; i += 192)
        ((float*)su)[i] = ((const float*)d_u)[i];
    __syncthreads();

    int b = blockIdx.y;
    int n = blockIdx.x;
    int s = tid;
    float as[HH] = {0.f, 0.f, 0.f, 0.f};
    float ad[HH] = {0.f, 0.f, 0.f, 0.f};

    const float* Xp = X + ((size_t)b * FIN * NN + n) * SS + s;
    #pragma unroll 8
    for (int f = 0; f < FIN; f++) {
        float x = Xp[(size_t)f * (NN * SS)];
        #pragma unroll
        for (int h = 0; h < HH; h++) {
            as[h] += x * su[0][h][f];
            ad[h] += x * su[1][h][f];
        }
    }
    float cb = b_attn[0];
    #pragma unroll
    for (int h = 0; h < HH; h++) {
        d_Ssrc[b][h][n][s] = (as[h] + d_c[0][h] + cb) * L2E;
        d_Sdst[b][h][n][s] = (ad[h] + d_c[1][h]) * L2E;   // n plays role m; coalesced
    }
}

// ---------------- K4: fused attention (denom + alpha-sum) ----------------
// grid (16, HH, BB) = 128 blocks, block 192, full Sdst[b,h] slab in smem.
// e(s,n,m) = Ssrc[n,s] + Sdst[m,s]; lrelu; exp2 (inputs pre-scaled by log2e).
// denom[m] = sum_{s unmasked} E ; alph[s] = mask * sum_m E / denom[m].
__global__ void __launch_bounds__(192) k_attn(const int* __restrict__ A) {
    extern __shared__ float smem[];
    float* slab  = smem;                    // [m][PITCH]  192*193
    float* ssv   = slab + NN * PITCH;       // 192
    float* rden  = ssv + SS;                // 192
    float* aph   = rden + NN;               // 192
    int*   slist = (int*)(aph + SS);        // 192
    int*   cntp  = slist + SS;              // 1

    int tid = threadIdx.x;
    int h = blockIdx.y, b = blockIdx.z;
    int nbase = blockIdx.x * CH;

    // load slab: global [m][s] -> smem [m*PITCH + s], float4 global reads
    {
        const float4* src = (const float4*)&d_Sdst[b][h][0][0];
        for (int i = tid; i < NN * SS / 4; i += 192) {
            float4 v = src[i];
            int m = (i * 4) / SS, s = (i * 4) % SS;
            float* dst = slab + m * PITCH + s;
            dst[0] = v.x; dst[1] = v.y; dst[2] = v.z; dst[3] = v.w;
        }
        if (tid == 0) *cntp = 0;
    }
    __syncthreads();

    for (int ni = 0; ni < CH; ni++) {
        int n = nbase + ni;
        // stage per-n data + compact unmasked-s list (order irrelevant)
        ssv[tid] = d_Ssrc[b][h][n][tid];
        aph[tid] = 0.f;
        int mk = A[tid * NN + n];
        if (mk) { int p = atomicAdd(cntp, 1); slist[p] = tid; }
        __syncthreads();
        int c = *cntp;

        // pass 1: thread = m, sum over unmasked s
        {
            float* myrow = slab + tid * PITCH;
            float a0 = 0.f, a1 = 0.f, a2 = 0.f, a3 = 0.f;
            int i = 0;
            for (; i + 4 <= c; i += 4) {
                int s0 = slist[i], s1 = slist[i+1], s2 = slist[i+2], s3 = slist[i+3];
                float t0 = ssv[s0] + myrow[s0];
                float t1 = ssv[s1] + myrow[s1];
                float t2 = ssv[s2] + myrow[s2];
                float t3 = ssv[s3] + myrow[s3];
                a0 += exp2f(fmaxf(t0, NEG * t0));
                a1 += exp2f(fmaxf(t1, NEG * t1));
                a2 += exp2f(fmaxf(t2, NEG * t2));
                a3 += exp2f(fmaxf(t3, NEG * t3));
            }
            for (; i < c; i++) {
                int s0 = slist[i];
                float t0 = ssv[s0] + myrow[s0];
                a0 += exp2f(fmaxf(t0, NEG * t0));
            }
            rden[tid] = __fdividef(1.f, (a0 + a1) + (a2 + a3));
        }
        __syncthreads();

        // pass 2: compacted thread t -> s = slist[t], sum over all m
        if (tid < c) {
            int s = slist[tid];
            float sv = ssv[s];
            const float* col = slab + s;   // + m*PITCH
            float a0 = 0.f, a1 = 0.f;
            #pragma unroll 4
            for (int m = 0; m < NN; m += 2) {
                float t0 = sv + col[m * PITCH];
                float t1 = sv + col[(m + 1) * PITCH];
                a0 += exp2f(fmaxf(t0, NEG * t0)) * rden[m];
                a1 += exp2f(fmaxf(t1, NEG * t1)) * rden[m + 1];
            }
            aph[s] = a0 + a1;
        }
        __syncthreads();

        d_alph[b][h][n][tid] = aph[tid];
        if (tid == 0) *cntp = 0;
        __syncthreads();
    }
}

// ---------------- K5: out[b, h*64+d, n, s] = alph[b,h,n,s] * sum_g[c] ----------------
__global__ void k_out(float* __restrict__ out) {
    int idx = blockIdx.x * 256 + threadIdx.x;  // float4 index
    int s4 = idx % 48;
    int n  = (idx / 48) % NN;
    int c  = (idx / (48 * NN)) % CC;
    int b  =  idx / (48 * NN * CC);
    int h  = c >> 6;
    float4 a = ((const float4*)&d_alph[b][h][n][0])[s4];
    float  g = d_sumg[c];
    ((float4*)out)[idx] = make_float4(a.x * g, a.y * g, a.z * g, a.w * g);
}

extern "C" void kernel_launch(void* const* d_in, const int* in_sizes, int n_in,
                              void* d_out, int out_size) {
    const float* X      = (const float*)d_in[0];
    const int*   A      = (const int*)  d_in[1];
    const float* W_lin  = (const float*)d_in[2];
    const float* b_lin  = (const float*)d_in[3];
    const float* W_attn = (const float*)d_in[4];
    const float* b_attn = (const float*)d_in[5];
    float* out = (float*)d_out;

    const int SMEM_ATTN = (NN * PITCH + SS + NN + SS) * 4 + (SS + 4) * 4;
    cudaFuncSetAttribute(k_attn, cudaFuncAttributeMaxDynamicSharedMemorySize, SMEM_ATTN);

    k_prep<<<1, 128>>>(W_lin, b_lin, W_attn);
    k_sumx<<<BB * FIN, 256>>>(X);
    k_sumg<<<1, 256>>>(W_lin, b_lin);
    k_proj<<<dim3(NN, BB), 192>>>(X, b_attn);
    k_attn<<<dim3(NN / CH, HH, BB), 192, SMEM_ATTN>>>(A);
    k_out<<<18432, 256>>>(out);
}

// round 3
// speedup vs baseline: 1.3092x; 1.2377x over previous
#include <cuda_runtime.h>

#define BB 2
#define FIN 128
#define NN 192
#define SS 192
#define HH 4
#define DD 64
#define CC 256          // H*D
#define NEG 0.2f
#define TOTF 73728.0f   // B*S*N
#define L2E 1.44269504088896f
#define CH 12           // n per attn block -> grid 16*4*2 = 128 blocks (1 wave)
#define PITCH 193       // smem slab pitch (conflict-free rows)
#define TPA 576         // threads in k_attn

__device__ __forceinline__ float ex2(float x) {
    float r; asm("ex2.approx.ftz.f32 %0, %1;" : "=f"(r) : "f"(x)); return r;
}

// ---------------- scratch (device globals; no allocation) ----------------
__device__ float d_u[2][HH][FIN];
__device__ float d_c[2][HH];
__device__ float d_sumx[BB * FIN];       // per (b,f) sums of X (atomically built)
__device__ float d_sumg[CC];
__device__ float d_Ssrc[BB][HH][NN][SS]; // (src + c_src + b_attn) * log2e   [n][s]
__device__ float d_Sdst[BB][HH][NN][SS]; // (dst + c_dst) * log2e            [m][s]

// ---------------- K0: u vectors + bias constants + zero sumx ----------------
__global__ void k_prep(const float* __restrict__ W_lin,
                       const float* __restrict__ b_lin,
                       const float* __restrict__ W_attn) {
    int f = threadIdx.x;  // 128 threads
    d_sumx[f] = 0.f;
    d_sumx[f + FIN] = 0.f;
    #pragma unroll
    for (int h = 0; h < HH; h++) {
        float as = 0.f, ad = 0.f;
        #pragma unroll 8
        for (int d = 0; d < DD; d++) {
            float w = W_lin[f * CC + h * DD + d];
            as += w * W_attn[d];
            ad += w * W_attn[DD + d];
        }
        d_u[0][h][f] = as;
        d_u[1][h][f] = ad;
    }
    if (f < HH) {
        int h = f;
        float cs = 0.f, cd = 0.f;
        for (int d = 0; d < DD; d++) {
            cs += b_lin[h * DD + d] * W_attn[d];
            cd += b_lin[h * DD + d] * W_attn[DD + d];
        }
        d_c[0][h] = cs;
        d_c[1][h] = cd;
    }
}

// ---------------- K1: projections + X row-sum fold-in ----------------
// grid (192, BB), block 192 (=s)
__global__ void __launch_bounds__(192) k_proj(const float* __restrict__ X,
                                              const float* __restrict__ b_attn) {
    __shared__ float su[2][HH][FIN];
    __shared__ float sxf[FIN];
    int tid = threadIdx.x;
    #pragma unroll
    for (int i = tid; i < 2 * HH * FIN; i += 192)
        ((float*)su)[i] = ((const float*)d_u)[i];
    if (tid < FIN) sxf[tid] = 0.f;
    __syncthreads();

    int b = blockIdx.y;
    int n = blockIdx.x;
    int s = tid;
    int lane = tid & 31;
    float as[HH] = {0.f, 0.f, 0.f, 0.f};
    float ad[HH] = {0.f, 0.f, 0.f, 0.f};

    const float* Xp = X + ((size_t)b * FIN * NN + n) * SS + s;
    const size_t FST = (size_t)NN * SS;

    for (int f0 = 0; f0 < FIN; f0 += 16) {
        float xv[16];
        #pragma unroll
        for (int k = 0; k < 16; k++) xv[k] = Xp[(f0 + k) * FST];
        #pragma unroll
        for (int k = 0; k < 16; k++) {
            float x = xv[k];
            #pragma unroll
            for (int h = 0; h < HH; h++) {
                as[h] += x * su[0][h][f0 + k];
                ad[h] += x * su[1][h][f0 + k];
            }
            // warp-reduce x for the X row-sum (per f)
            float r = x;
            r += __shfl_xor_sync(0xFFFFFFFFu, r, 16);
            r += __shfl_xor_sync(0xFFFFFFFFu, r, 8);
            r += __shfl_xor_sync(0xFFFFFFFFu, r, 4);
            r += __shfl_xor_sync(0xFFFFFFFFu, r, 2);
            r += __shfl_xor_sync(0xFFFFFFFFu, r, 1);
            if (lane == 0) atomicAdd(&sxf[f0 + k], r);
        }
    }
    float cb = b_attn[0];
    #pragma unroll
    for (int h = 0; h < HH; h++) {
        d_Ssrc[b][h][n][s] = (as[h] + d_c[0][h] + cb) * L2E;
        d_Sdst[b][h][n][s] = (ad[h] + d_c[1][h]) * L2E;
    }
    __syncthreads();
    if (tid < FIN) atomicAdd(&d_sumx[b * FIN + tid], sxf[tid]);
}

// ---------------- K2: sum_g ----------------
__global__ void k_sumg(const float* __restrict__ W_lin,
                       const float* __restrict__ b_lin) {
    int c = threadIdx.x;  // 256 threads
    float acc = 0.f;
    #pragma unroll 8
    for (int f = 0; f < FIN; f++)
        acc += (d_sumx[f] + d_sumx[FIN + f]) * W_lin[f * CC + c];
    d_sumg[c] = acc + TOTF * b_lin[c];
}

// ---------------- K3: fused attention + output write ----------------
// grid (16, HH, BB) = 128 blocks, block 576.
__global__ void __launch_bounds__(TPA) k_attn(const int* __restrict__ A,
                                              float* __restrict__ out) {
    extern __shared__ float smem[];
    float* slab  = smem;                       // [m][PITCH] 192*193
    float* ssv   = slab + NN * PITCH;          // 192
    float* rden  = ssv + SS;                   // 192
    float* part  = rden + NN;                  // 576
    float* aph   = part + TPA;                 // 192 (16B aligned)
    float* sgs   = aph + SS;                   // 64
    int*   msk   = (int*)(sgs + 64);           // 192
    int*   slist = msk + SS;                   // 192
    int*   wcnt  = slist + SS;                 // 6

    int tid = threadIdx.x;
    int h = blockIdx.y, b = blockIdx.z;
    int nbase = blockIdx.x * CH;
    int jj = tid / 192;       // 0..2
    int ii = tid - jj * 192;  // 0..191

    // stage slab + sum_g slice
    {
        const float4* src = (const float4*)&d_Sdst[b][h][0][0];
        #pragma unroll
        for (int i = tid; i < NN * SS / 4; i += TPA) {
            float4 v = src[i];
            int e = i * 4;
            float* dst = slab + (e / SS) * PITCH + (e % SS);
            dst[0] = v.x; dst[1] = v.y; dst[2] = v.z; dst[3] = v.w;
        }
        if (tid < 64) sgs[tid] = d_sumg[h * 64 + tid];
    }
    __syncthreads();

    for (int ni = 0; ni < CH; ni++) {
        int n = nbase + ni;
        // stage src row + ordered compaction of unmasked s
        if (tid < SS) {
            ssv[tid] = d_Ssrc[b][h][n][tid];
            int mk = (A[tid * NN + n] != 0);
            msk[tid] = mk;
            unsigned bal = __ballot_sync(0xFFFFFFFFu, mk);
            if ((tid & 31) == 0) wcnt[tid >> 5] = __popc(bal);
        }
        __syncthreads();
        int c = wcnt[0] + wcnt[1] + wcnt[2] + wcnt[3] + wcnt[4] + wcnt[5];
        if (tid < SS) {
            int w = tid >> 5, l = tid & 31;
            unsigned bal = __ballot_sync(0xFFFFFFFFu, msk[tid]);
            int base = 0;
            #pragma unroll
            for (int i = 0; i < 5; i++) base += (i < w) ? wcnt[i] : 0;
            if (msk[tid]) slist[base + __popc(bal & ((1u << l) - 1u))] = tid;
        }
        __syncthreads();

        // pass 1: denom. thread (m=ii, chunk jj) sums s over its slice of slist
        {
            const float* myrow = slab + ii * PITCH;
            int i0 = (c * jj) / 3, i1 = (c * (jj + 1)) / 3;
            float a0 = 0.f, a1 = 0.f;
            int i = i0;
            for (; i + 2 <= i1; i += 2) {
                int s0 = slist[i], s1 = slist[i + 1];
                float t0 = ssv[s0] + myrow[s0];
                float t1 = ssv[s1] + myrow[s1];
                a0 += ex2(fmaxf(t0, NEG * t0));
                a1 += ex2(fmaxf(t1, NEG * t1));
            }
            if (i < i1) {
                int s0 = slist[i];
                float t0 = ssv[s0] + myrow[s0];
                a0 += ex2(fmaxf(t0, NEG * t0));
            }
            part[jj * 192 + ii] = a0 + a1;
        }
        __syncthreads();
        if (tid < NN)
            rden[tid] = __fdividef(1.f, part[tid] + part[192 + tid] + part[384 + tid]);
        __syncthreads();

        // pass 2: alpha row-sums. thread (list idx ii, m-chunk jj of 64)
        if (ii < c) {
            int s = slist[ii];
            float sv = ssv[s];
            const float* col = slab + s + jj * 64 * PITCH;
            const float* rd  = rden + jj * 64;
            float a0 = 0.f, a1 = 0.f;
            #pragma unroll 8
            for (int m = 0; m < 64; m += 2) {
                float t0 = sv + col[m * PITCH];
                float t1 = sv + col[(m + 1) * PITCH];
                a0 += ex2(fmaxf(t0, NEG * t0)) * rd[m];
                a1 += ex2(fmaxf(t1, NEG * t1)) * rd[m + 1];
            }
            part[jj * 192 + s] = a0 + a1;
        }
        __syncthreads();
        if (tid < SS)
            aph[tid] = msk[tid] ? (part[tid] + part[192 + tid] + part[384 + tid]) : 0.f;
        __syncthreads();

        // output write: out[b, h*64+d, n, s] = aph[s] * sumg[h*64+d], float4 over s
        {
            float4* outp = (float4*)out;
            size_t cb = (size_t)b * CC + h * 64;
            #pragma unroll
            for (int idx = tid; idx < 64 * 48; idx += TPA) {
                int d = idx / 48, s4 = idx - d * 48;
                float g = sgs[d];
                float4 a = ((const float4*)aph)[s4];
                outp[((cb + d) * NN + n) * 48 + s4] =
                    make_float4(a.x * g, a.y * g, a.z * g, a.w * g);
            }
        }
        __syncthreads();
    }
}

extern "C" void kernel_launch(void* const* d_in, const int* in_sizes, int n_in,
                              void* d_out, int out_size) {
    const float* X      = (const float*)d_in[0];
    const int*   A      = (const int*)  d_in[1];
    const float* W_lin  = (const float*)d_in[2];
    const float* b_lin  = (const float*)d_in[3];
    const float* W_attn = (const float*)d_in[4];
    const float* b_attn = (const float*)d_in[5];
    float* out = (float*)d_out;

    const int SMEM_ATTN = (NN * PITCH + SS + NN + TPA + SS + 64) * 4 + (SS + SS + 8) * 4;
    static int configured = 0;
    if (!configured) {
        cudaFuncSetAttribute(k_attn, cudaFuncAttributeMaxDynamicSharedMemorySize, SMEM_ATTN);
        configured = 1;
    }

    k_prep<<<1, 128>>>(W_lin, b_lin, W_attn);
    k_proj<<<dim3(NN, BB), 192>>>(X, b_attn);
    k_sumg<<<1, 256>>>(W_lin, b_lin);
    k_attn<<<dim3(NN / CH, HH, BB), TPA, SMEM_ATTN>>>(A, out);
}

// round 4
// speedup vs baseline: 1.3810x; 1.0548x over previous
#include <cuda_runtime.h>
#include <cuda_fp16.h>

#define BB 2
#define FIN 128
#define NN 192
#define SS 192
#define HH 4
#define DD 64
#define CC 256          // H*D
#define NEG 0.2f
#define TOTF 73728.0f   // B*S*N
#define L2E 1.44269504088896f
#define CH 12           // n per attn block -> 16*4*2 = 128 blocks (1 wave)
#define PITCH 193       // fp32 slab pitch (conflict-free rows/cols)
#define EPITCH 194      // fp16 E pitch: EPITCH/2 = 97 odd -> conflict-free
#define TPA 768         // threads in k_attn

__device__ __forceinline__ float ex2(float x) {
    float r; asm("ex2.approx.ftz.f32 %0, %1;" : "=f"(r) : "f"(x)); return r;
}

// ---------------- scratch (device globals; no allocation) ----------------
__device__ float d_u[2][HH][FIN];
__device__ float d_c[2][HH];
__device__ float d_sumx[BB * FIN];
__device__ float d_sumg[CC];
__device__ float d_SsrcP[2][BB][HH][NN][SS];  // f-half partials, pre-scaled by log2e
__device__ float d_SdstP[2][BB][HH][NN][SS];

// ---------------- K0: u vectors + bias constants ----------------
__global__ void k_prep(const float* __restrict__ W_lin,
                       const float* __restrict__ b_lin,
                       const float* __restrict__ W_attn) {
    int f = threadIdx.x;  // 128 threads
    #pragma unroll
    for (int h = 0; h < HH; h++) {
        float as = 0.f, ad = 0.f;
        #pragma unroll 8
        for (int d = 0; d < DD; d++) {
            float w = W_lin[f * CC + h * DD + d];
            as += w * W_attn[d];
            ad += w * W_attn[DD + d];
        }
        d_u[0][h][f] = as;
        d_u[1][h][f] = ad;
    }
    if (f < HH) {
        int h = f;
        float cs = 0.f, cd = 0.f;
        for (int d = 0; d < DD; d++) {
            cs += b_lin[h * DD + d] * W_attn[d];
            cd += b_lin[h * DD + d] * W_attn[DD + d];
        }
        d_c[0][h] = cs;
        d_c[1][h] = cd;
    }
}

// ---------------- K1: projections, f split in 2 halves ----------------
// grid (192, 2, BB), block 192 (=s)
__global__ void __launch_bounds__(192) k_proj(const float* __restrict__ X,
                                              const float* __restrict__ b_attn) {
    __shared__ float su[2][HH][64];
    int tid = threadIdx.x;
    int half = blockIdx.y, b = blockIdx.z, n = blockIdx.x;
    for (int i = tid; i < 2 * HH * 64; i += 192) {
        int t = i / (HH * 64), r = i % (HH * 64);
        su[t][r / 64][r % 64] = d_u[t][r / 64][half * 64 + (r % 64)];
    }
    __syncthreads();

    int s = tid;
    float as[HH] = {0.f, 0.f, 0.f, 0.f};
    float ad[HH] = {0.f, 0.f, 0.f, 0.f};
    const float* Xp = X + (((size_t)b * FIN + half * 64) * NN + n) * SS + s;
    const size_t FST = (size_t)NN * SS;

    for (int f0 = 0; f0 < 64; f0 += 16) {
        float xv[16];
        #pragma unroll
        for (int k = 0; k < 16; k++) xv[k] = Xp[(f0 + k) * FST];
        #pragma unroll
        for (int k = 0; k < 16; k++) {
            float x = xv[k];
            #pragma unroll
            for (int h = 0; h < HH; h++) {
                as[h] += x * su[0][h][f0 + k];
                ad[h] += x * su[1][h][f0 + k];
            }
        }
    }
    float cb = b_attn[0];
    #pragma unroll
    for (int h = 0; h < HH; h++) {
        float cs = (half == 0) ? (d_c[0][h] + cb) : 0.f;
        float cd = (half == 0) ? d_c[1][h] : 0.f;
        d_SsrcP[half][b][h][n][s] = (as[h] + cs) * L2E;
        d_SdstP[half][b][h][n][s] = (ad[h] + cd) * L2E;
    }
}

// ---------------- K2: X row sums (runs after k_proj -> X resident in L2) ----------------
__global__ void k_sumx(const float* __restrict__ X) {
    int bf = blockIdx.x;  // 256 blocks
    const float4* p = (const float4*)(X + (size_t)bf * (NN * SS));
    float acc = 0.f;
    for (int i = threadIdx.x; i < NN * SS / 4; i += 256) {
        float4 v = p[i];
        acc += (v.x + v.y) + (v.z + v.w);
    }
    __shared__ float sm[256];
    sm[threadIdx.x] = acc;
    __syncthreads();
    #pragma unroll
    for (int st = 128; st > 0; st >>= 1) {
        if (threadIdx.x < st) sm[threadIdx.x] += sm[threadIdx.x + st];
        __syncthreads();
    }
    if (threadIdx.x == 0) d_sumx[bf] = sm[0];
}

// ---------------- K3: sum_g ----------------
__global__ void k_sumg(const float* __restrict__ W_lin,
                       const float* __restrict__ b_lin) {
    int c = threadIdx.x;  // 256 threads
    float acc = 0.f;
    #pragma unroll 8
    for (int f = 0; f < FIN; f++)
        acc += (d_sumx[f] + d_sumx[FIN + f]) * W_lin[f * CC + c];
    d_sumg[c] = acc + TOTF * b_lin[c];
}

// ---------------- K4: fused attention + output ----------------
// grid (16, HH, BB) = 128 blocks, block 768.
// smem word layout (total 57480 words = 229920 B):
//   slab  [0,37056)        fp32 dst slab [m][PITCH]
//   Eh    [37056,55680)    fp16 E [m][EPITCH] (37248 halves)
//   ssv   [55680,55872)
//   rden  [55872,56064)
//   part  [56064,56832)    768
//   aph   [56832,57024)    192 (16B aligned)
//   sgs   [57024,57088)    64
//   msk   [57088,57280)    192 int
//   slist [57280,57472)    192 int
//   wcnt  [57472,57480)    8 int
__global__ void __launch_bounds__(TPA) k_attn(const int* __restrict__ A,
                                              float* __restrict__ out) {
    extern __shared__ float smem[];
    float*  slab  = smem;
    __half* Eh    = (__half*)(smem + 37056);
    float*  ssv   = smem + 55680;
    float*  rden  = smem + 55872;
    float*  part  = smem + 56064;
    float*  aph   = smem + 56832;
    float*  sgs   = smem + 57024;
    int*    msk   = (int*)(smem + 57088);
    int*    slist = (int*)(smem + 57280);
    int*    wcnt  = (int*)(smem + 57472);

    int tid = threadIdx.x;
    int h = blockIdx.y, b = blockIdx.z;
    int nbase = blockIdx.x * CH;
    int jj = tid / 192;       // 0..3
    int ii = tid - jj * 192;  // 0..191

    // stage slab (sum of f-half partials) + sum_g slice
    {
        const float4* p0 = (const float4*)&d_SdstP[0][b][h][0][0];
        const float4* p1 = (const float4*)&d_SdstP[1][b][h][0][0];
        #pragma unroll
        for (int i = tid; i < NN * SS / 4; i += TPA) {
            float4 v0 = p0[i], v1 = p1[i];
            int e = i * 4;
            float* dst = slab + (e / SS) * PITCH + (e % SS);
            dst[0] = v0.x + v1.x; dst[1] = v0.y + v1.y;
            dst[2] = v0.z + v1.z; dst[3] = v0.w + v1.w;
        }
        if (tid < 64) sgs[tid] = d_sumg[h * 64 + tid];
    }
    __syncthreads();

    for (int ni = 0; ni < CH; ni++) {
        int n = nbase + ni;
        // stage src row + ordered compaction of unmasked s
        if (tid < SS) {
            ssv[tid] = d_SsrcP[0][b][h][n][tid] + d_SsrcP[1][b][h][n][tid];
            int mk = (A[tid * NN + n] != 0);
            msk[tid] = mk;
            unsigned bal = __ballot_sync(0xFFFFFFFFu, mk);
            if ((tid & 31) == 0) wcnt[tid >> 5] = __popc(bal);
        }
        __syncthreads();
        int c = wcnt[0] + wcnt[1] + wcnt[2] + wcnt[3] + wcnt[4] + wcnt[5];
        if (tid < SS) {
            int w = tid >> 5, l = tid & 31;
            unsigned bal = __ballot_sync(0xFFFFFFFFu, msk[tid]);
            int base = 0;
            #pragma unroll
            for (int i = 0; i < 5; i++) base += (i < w) ? wcnt[i] : 0;
            if (msk[tid]) slist[base + __popc(bal & ((1u << l) - 1u))] = tid;
        }
        __syncthreads();

        // pass 1: compute E (store fp16) + denom partials. thread (m=ii, s-chunk jj)
        {
            const float* myrow = slab + ii * PITCH;
            __half* myE = Eh + ii * EPITCH;
            int i0 = (c * jj) >> 2, i1 = (c * (jj + 1)) >> 2;
            float a0 = 0.f, a1 = 0.f;
            int i = i0;
            for (; i + 2 <= i1; i += 2) {
                int s0 = slist[i], s1 = slist[i + 1];
                float t0 = ssv[s0] + myrow[s0];
                float t1 = ssv[s1] + myrow[s1];
                float e0 = ex2(fmaxf(t0, NEG * t0));
                float e1 = ex2(fmaxf(t1, NEG * t1));
                myE[s0] = __float2half(e0);
                myE[s1] = __float2half(e1);
                a0 += e0; a1 += e1;
            }
            if (i < i1) {
                int s0 = slist[i];
                float t0 = ssv[s0] + myrow[s0];
                float e0 = ex2(fmaxf(t0, NEG * t0));
                myE[s0] = __float2half(e0);
                a0 += e0;
            }
            part[jj * 192 + ii] = a0 + a1;
        }
        __syncthreads();
        if (tid < NN)
            rden[tid] = __fdividef(1.f,
                part[tid] + part[192 + tid] + part[384 + tid] + part[576 + tid]);
        __syncthreads();

        // pass 2: alpha row-sums from stored E. thread (s=ii, m-chunk jj of 48)
        {
            const __half* col = Eh + ii + (jj * 48) * EPITCH;
            const float* rd = rden + jj * 48;
            float a0 = 0.f, a1 = 0.f;
            #pragma unroll 8
            for (int m = 0; m < 48; m += 2) {
                a0 += __half2float(col[m * EPITCH]) * rd[m];
                a1 += __half2float(col[(m + 1) * EPITCH]) * rd[m + 1];
            }
            part[jj * 192 + ii] = a0 + a1;
        }
        __syncthreads();
        if (tid < SS)
            aph[tid] = msk[tid]
                ? (part[tid] + part[192 + tid] + part[384 + tid] + part[576 + tid])
                : 0.f;
        __syncthreads();

        // output: out[b, h*64+d, n, s] = aph[s] * sumg[h*64+d], float4 over s
        {
            float4* outp = (float4*)out;
            size_t cb0 = (size_t)b * CC + h * 64;
            #pragma unroll
            for (int idx = tid; idx < 64 * 48; idx += TPA) {
                int d = idx / 48, s4 = idx - d * 48;
                float g = sgs[d];
                float4 a = ((const float4*)aph)[s4];
                outp[((cb0 + d) * NN + n) * 48 + s4] =
                    make_float4(a.x * g, a.y * g, a.z * g, a.w * g);
            }
        }
        __syncthreads();
    }
}

extern "C" void kernel_launch(void* const* d_in, const int* in_sizes, int n_in,
                              void* d_out, int out_size) {
    const float* X      = (const float*)d_in[0];
    const int*   A      = (const int*)  d_in[1];
    const float* W_lin  = (const float*)d_in[2];
    const float* b_lin  = (const float*)d_in[3];
    const float* W_attn = (const float*)d_in[4];
    const float* b_attn = (const float*)d_in[5];
    float* out = (float*)d_out;

    const int SMEM_ATTN = 57480 * 4;  // 229920 B
    cudaFuncSetAttribute(k_attn, cudaFuncAttributeMaxDynamicSharedMemorySize, SMEM_ATTN);

    k_prep<<<1, 128>>>(W_lin, b_lin, W_attn);
    k_proj<<<dim3(NN, 2, BB), 192>>>(X, b_attn);
    k_sumx<<<BB * FIN, 256>>>(X);
    k_sumg<<<1, 256>>>(W_lin, b_lin);
    k_attn<<<dim3(NN / CH, HH, BB), TPA, SMEM_ATTN>>>(A, out);
}

// round 5
// speedup vs baseline: 1.4785x; 1.0707x over previous
#include <cuda_runtime.h>
#include <cuda_fp16.h>

#define BB 2
#define FIN 128
#define NN 192
#define SS 192
#define HH 4
#define DD 64
#define CC 256          // H*D
#define NEG 0.2f
#define TOTF 73728.0f   // B*S*N
#define L2E 1.44269504088896f
#define CH 12           // n per attn block -> 16*4*2 = 128 blocks (1 wave)
#define NW 5            // work chunks in k_attn
#define TPA 960         // threads in k_attn (192*NW)
#define PITCH 193       // fp32 slab pitch (conflict-free)
#define EPITCH 194      // fp16 E pitch in halves (word stride 97, conflict-free)

// smem word offsets
#define W_SLAB 0
#define W_EH   37056
#define W_SSV  55680
#define W_RDEN 55872
#define W_PART 56064
#define W_APH  57024
#define W_SGS  57216
#define W_SL   57280
#define W_CNT  57856
#define W_TOT  57868    // 231472 bytes

__device__ __forceinline__ float ex2(float x) {
    float r; asm("ex2.approx.ftz.f32 %0, %1;" : "=f"(r) : "f"(x)); return r;
}

// ---------------- scratch ----------------
__device__ float d_u[2][HH][FIN];
__device__ float d_c[2][HH];
__device__ float d_sumx[BB * FIN];
__device__ float d_SsrcP[2][BB][HH][NN][SS];  // f-half partials, pre-scaled log2e
__device__ float d_SdstP[2][BB][HH][NN][SS];

// ---------------- K0: u vectors + bias constants ----------------
__global__ void k_prep(const float* __restrict__ W_lin,
                       const float* __restrict__ b_lin,
                       const float* __restrict__ W_attn) {
    int f = threadIdx.x;  // 128
    #pragma unroll
    for (int h = 0; h < HH; h++) {
        float as = 0.f, ad = 0.f;
        #pragma unroll 8
        for (int d = 0; d < DD; d++) {
            float w = W_lin[f * CC + h * DD + d];
            as += w * W_attn[d];
            ad += w * W_attn[DD + d];
        }
        d_u[0][h][f] = as;
        d_u[1][h][f] = ad;
    }
    if (f < HH) {
        int h = f;
        float cs = 0.f, cd = 0.f;
        for (int d = 0; d < DD; d++) {
            cs += b_lin[h * DD + d] * W_attn[d];
            cd += b_lin[h * DD + d] * W_attn[DD + d];
        }
        d_c[0][h] = cs;
        d_c[1][h] = cd;
    }
}

// ---------------- K1: projections, f split in 2 halves ----------------
// grid (192, 2, BB), block 192 (=s)
__global__ void __launch_bounds__(192) k_proj(const float* __restrict__ X,
                                              const float* __restrict__ b_attn) {
    __shared__ float su[2][HH][64];
    int tid = threadIdx.x;
    int half = blockIdx.y, b = blockIdx.z, n = blockIdx.x;
    for (int i = tid; i < 2 * HH * 64; i += 192) {
        int t = i / (HH * 64), r = i % (HH * 64);
        su[t][r / 64][r % 64] = d_u[t][r / 64][half * 64 + (r % 64)];
    }
    __syncthreads();

    int s = tid;
    float as[HH] = {0.f, 0.f, 0.f, 0.f};
    float ad[HH] = {0.f, 0.f, 0.f, 0.f};
    const float* Xp = X + (((size_t)b * FIN + half * 64) * NN + n) * SS + s;
    const size_t FST = (size_t)NN * SS;

    for (int f0 = 0; f0 < 64; f0 += 16) {
        float xv[16];
        #pragma unroll
        for (int k = 0; k < 16; k++) xv[k] = Xp[(f0 + k) * FST];
        #pragma unroll
        for (int k = 0; k < 16; k++) {
            float x = xv[k];
            #pragma unroll
            for (int h = 0; h < HH; h++) {
                as[h] += x * su[0][h][f0 + k];
                ad[h] += x * su[1][h][f0 + k];
            }
        }
    }
    float cb = b_attn[0];
    #pragma unroll
    for (int h = 0; h < HH; h++) {
        float cs = (half == 0) ? (d_c[0][h] + cb) : 0.f;
        float cd = (half == 0) ? d_c[1][h] : 0.f;
        d_SsrcP[half][b][h][n][s] = (as[h] + cs) * L2E;
        d_SdstP[half][b][h][n][s] = (ad[h] + cd) * L2E;
    }
}

// ---------------- K2: X row sums (X in L2 after k_proj) ----------------
__global__ void k_sumx(const float* __restrict__ X) {
    int bf = blockIdx.x;  // 256 blocks
    const float4* p = (const float4*)(X + (size_t)bf * (NN * SS));
    float acc = 0.f;
    for (int i = threadIdx.x; i < NN * SS / 4; i += 256) {
        float4 v = p[i];
        acc += (v.x + v.y) + (v.z + v.w);
    }
    __shared__ float sm[256];
    sm[threadIdx.x] = acc;
    __syncthreads();
    #pragma unroll
    for (int st = 128; st > 0; st >>= 1) {
        if (threadIdx.x < st) sm[threadIdx.x] += sm[threadIdx.x + st];
        __syncthreads();
    }
    if (threadIdx.x == 0) d_sumx[bf] = sm[0];
}

// ---------------- K3: fused attention + sum_g + output ----------------
// grid (16, HH, BB) = 128 blocks, block 960.
__global__ void __launch_bounds__(TPA) k_attn(const int* __restrict__ A,
                                              const float* __restrict__ W_lin,
                                              const float* __restrict__ b_lin,
                                              float* __restrict__ out) {
    extern __shared__ float smem[];
    float*         slab  = smem + W_SLAB;             // [m][PITCH]
    __half*        Eh    = (__half*)(smem + W_EH);    // [s][EPITCH]
    float*         ssv   = smem + W_SSV;
    float*         rden  = smem + W_RDEN;
    float*         part  = smem + W_PART;             // [NW][192]
    float*         aph   = smem + W_APH;              // doubles as wcnt in prologue
    float*         sgs   = smem + W_SGS;
    unsigned char* slist = (unsigned char*)(smem + W_SL);  // [CH][192]
    int*           cnt   = (int*)(smem + W_CNT);
    int*           wcnt  = (int*)aph;                 // [CH][6] (prologue only)

    int tid = threadIdx.x;
    int h = blockIdx.y, b = blockIdx.z;
    int nbase = blockIdx.x * CH;
    int jj = tid / 192;       // 0..4
    int ii = tid - jj * 192;  // 0..191

    // ---- prologue phase A: slab staging + mask ballots + sum_g partials ----
    {
        const float4* p0 = (const float4*)&d_SdstP[0][b][h][0][0];
        const float4* p1 = (const float4*)&d_SdstP[1][b][h][0][0];
        #pragma unroll
        for (int i = tid; i < NN * SS / 4; i += TPA) {
            float4 v0 = p0[i], v1 = p1[i];
            int e = i * 4;
            float* dst = slab + (e / SS) * PITCH + (e % SS);
            dst[0] = v0.x + v1.x; dst[1] = v0.y + v1.y;
            dst[2] = v0.z + v1.z; dst[3] = v0.w + v1.w;
        }
    }
    unsigned bals[CH];
    int mkbits = 0;
    if (tid < SS) {
        #pragma unroll
        for (int ni = 0; ni < CH; ni++) {
            int mk = (A[tid * NN + nbase + ni] != 0);
            unsigned bal = __ballot_sync(0xFFFFFFFFu, mk);
            bals[ni] = bal;
            mkbits |= mk << ni;
            if ((tid & 31) == 0) wcnt[ni * 6 + (tid >> 5)] = __popc(bal);
        }
    }
    if (tid >= 256 && tid < 768) {
        int t = tid - 256, d = t >> 3, k = t & 7;
        float acc = 0.f;
        const float* wp = W_lin + h * 64 + d;
        #pragma unroll
        for (int f = k * 16; f < k * 16 + 16; f++)
            acc += (d_sumx[f] + d_sumx[FIN + f]) * wp[f * CC];
        part[tid] = acc;
    }
    __syncthreads();

    // ---- prologue phase B: build lists, counts, sgs, first ssv ----
    if (tid < SS) {
        int w = tid >> 5, l = tid & 31;
        unsigned lmask = (1u << l) - 1u;
        #pragma unroll
        for (int ni = 0; ni < CH; ni++) {
            if ((mkbits >> ni) & 1) {
                int base = 0;
                #pragma unroll
                for (int q = 0; q < 5; q++) base += (q < w) ? wcnt[ni * 6 + q] : 0;
                slist[ni * 192 + base + __popc(bals[ni] & lmask)] = (unsigned char)tid;
            }
        }
        ssv[tid] = d_SsrcP[0][b][h][nbase][tid] + d_SsrcP[1][b][h][nbase][tid];
    }
    if (tid >= 192 && tid < 204) {
        int ni = tid - 192;
        cnt[ni] = wcnt[ni * 6] + wcnt[ni * 6 + 1] + wcnt[ni * 6 + 2]
                + wcnt[ni * 6 + 3] + wcnt[ni * 6 + 4] + wcnt[ni * 6 + 5];
    }
    if (tid >= 256 && tid < 320) {
        int d = tid - 256;
        float s = 0.f;
        #pragma unroll
        for (int k = 0; k < 8; k++) s += part[256 + d * 8 + k];
        sgs[d] = s + TOTF * b_lin[h * 64 + d];
    }
    __syncthreads();

    int m0 = (jj == 0) ? 0 : (jj == 1) ? 40 : (jj == 2) ? 80 : (jj == 3) ? 120 : 156;
    int m1 = (jj == 0) ? 40 : (jj == 1) ? 80 : (jj == 2) ? 120 : (jj == 3) ? 156 : 192;

    for (int ni = 0; ni < CH; ni++) {
        int n = nbase + ni;
        int c = cnt[ni];

        // pass 1: E + denom partials. thread (m=ii, s-chunk jj over compacted list)
        {
            const float* myrow = slab + ii * PITCH;
            const unsigned char* sl = slist + ni * 192;
            int i0 = (c * jj) / NW, i1 = (c * (jj + 1)) / NW;
            float a0 = 0.f, a1 = 0.f;
            int i = i0;
            for (; i + 2 <= i1; i += 2) {
                int s0 = sl[i], s1 = sl[i + 1];
                float t0 = ssv[s0] + myrow[s0];
                float t1 = ssv[s1] + myrow[s1];
                float e0 = ex2(fmaxf(t0, NEG * t0));
                float e1 = ex2(fmaxf(t1, NEG * t1));
                Eh[s0 * EPITCH + ii] = __float2half(e0);
                Eh[s1 * EPITCH + ii] = __float2half(e1);
                a0 += e0; a1 += e1;
            }
            if (i < i1) {
                int s0 = sl[i];
                float t0 = ssv[s0] + myrow[s0];
                float e0 = ex2(fmaxf(t0, NEG * t0));
                Eh[s0 * EPITCH + ii] = __float2half(e0);
                a0 += e0;
            }
            part[jj * 192 + ii] = a0 + a1;
        }
        __syncthreads();
        if (tid < NN)
            rden[tid] = __fdividef(1.f, part[tid] + part[192 + tid] + part[384 + tid]
                                        + part[576 + tid] + part[768 + tid]);
        __syncthreads();

        // pass 2: alpha row-sums. thread (s=ii, m-chunk jj), contiguous half2
        {
            const __half2* row = (const __half2*)(Eh + ii * EPITCH);
            float a0 = 0.f, a1 = 0.f;
            #pragma unroll 4
            for (int m = m0; m < m1; m += 2) {
                float2 e = __half22float2(row[m >> 1]);
                a0 += e.x * rden[m];
                a1 += e.y * rden[m + 1];
            }
            part[jj * 192 + ii] = a0 + a1;
        }
        __syncthreads();
        if (tid < SS) {
            float sum = part[tid] + part[192 + tid] + part[384 + tid]
                      + part[576 + tid] + part[768 + tid];
            aph[tid] = (A[tid * NN + n] != 0) ? sum : 0.f;
            if (ni + 1 < CH)
                ssv[tid] = d_SsrcP[0][b][h][n + 1][tid] + d_SsrcP[1][b][h][n + 1][tid];
        }
        __syncthreads();

        // output: out[b, h*64+d, n, s] = aph[s] * sgs[d]; no trailing sync needed
        {
            float4* outp = (float4*)out;
            size_t cb0 = (size_t)b * CC + h * 64;
            #pragma unroll
            for (int idx = tid; idx < 64 * 48; idx += TPA) {
                int d = idx / 48, s4 = idx - d * 48;
                float g = sgs[d];
                float4 a = ((const float4*)aph)[s4];
                outp[((cb0 + d) * NN + n) * 48 + s4] =
                    make_float4(a.x * g, a.y * g, a.z * g, a.w * g);
            }
        }
    }
}

extern "C" void kernel_launch(void* const* d_in, const int* in_sizes, int n_in,
                              void* d_out, int out_size) {
    const float* X      = (const float*)d_in[0];
    const int*   A      = (const int*)  d_in[1];
    const float* W_lin  = (const float*)d_in[2];
    const float* b_lin  = (const float*)d_in[3];
    const float* W_attn = (const float*)d_in[4];
    const float* b_attn = (const float*)d_in[5];
    float* out = (float*)d_out;

    const int SMEM_ATTN = W_TOT * 4;  // 231472 B
    cudaFuncSetAttribute(k_attn, cudaFuncAttributeMaxDynamicSharedMemorySize, SMEM_ATTN);

    k_prep<<<1, 128>>>(W_lin, b_lin, W_attn);
    k_proj<<<dim3(NN, 2, BB), 192>>>(X, b_attn);
    k_sumx<<<BB * FIN, 256>>>(X);
    k_attn<<<dim3(NN / CH, HH, BB), TPA, SMEM_ATTN>>>(A, W_lin, b_lin, out);
}

// round 6
// speedup vs baseline: 1.5818x; 1.0699x over previous
#include <cuda_runtime.h>
#include <cuda_fp16.h>

#define BB 2
#define FIN 128
#define NN 192
#define SS 192
#define HH 4
#define DD 64
#define CC 256          // H*D
#define NEG 0.2f
#define TOTF 73728.0f   // B*S*N
#define L2E 1.44269504088896f
#define CH 12           // n per attn block -> 16*4*2 = 128 blocks (1 wave)
#define TPA 960
#define EPH 97          // half2 pitch (words) for slab/E: odd -> conflict-free

// smem word offsets
#define W_SLAB 0        // half2 [192 s][97]  (dst pairs)
#define W_EH   18624    // half2 [192 s][97]  (E pairs)
#define W_SSV  37248    // 192 f32
#define W_RDEN 37440    // 192 f32 (even -> float2 ok)
#define W_PART 37632    // 1920 f32 (10 chunks x 192)
#define W_APH  39552    // 192 f32 (16B aligned)
#define W_SGS  39744    // 64 f32
#define W_TOT  39808    // 159232 bytes

__device__ __forceinline__ unsigned h2ex2u(unsigned x) {
    unsigned r; asm("ex2.approx.f16x2 %0, %1;" : "=r"(r) : "r"(x)); return r;
}

// ---------------- scratch ----------------
__device__ float d_u[2][HH][FIN];
__device__ float d_c[2][HH];
__device__ float d_sumx[BB * FIN];
__device__ float d_SsrcP[2][BB][HH][NN][SS];  // f-half partials, pre-scaled log2e
__device__ float d_SdstP[2][BB][HH][NN][SS];

// ---------------- K0: u vectors + bias constants ----------------
__global__ void k_prep(const float* __restrict__ W_lin,
                       const float* __restrict__ b_lin,
                       const float* __restrict__ W_attn) {
    int f = threadIdx.x;  // 128
    #pragma unroll
    for (int h = 0; h < HH; h++) {
        float as = 0.f, ad = 0.f;
        #pragma unroll 8
        for (int d = 0; d < DD; d++) {
            float w = W_lin[f * CC + h * DD + d];
            as += w * W_attn[d];
            ad += w * W_attn[DD + d];
        }
        d_u[0][h][f] = as;
        d_u[1][h][f] = ad;
    }
    if (f < HH) {
        int h = f;
        float cs = 0.f, cd = 0.f;
        for (int d = 0; d < DD; d++) {
            cs += b_lin[h * DD + d] * W_attn[d];
            cd += b_lin[h * DD + d] * W_attn[DD + d];
        }
        d_c[0][h] = cs;
        d_c[1][h] = cd;
    }
}

// ---------------- K1: projections, f split in 2 halves ----------------
// grid (192, 2, BB), block 192 (=s)
__global__ void __launch_bounds__(192) k_proj(const float* __restrict__ X,
                                              const float* __restrict__ b_attn) {
    __shared__ float su[2][HH][64];
    int tid = threadIdx.x;
    int half = blockIdx.y, b = blockIdx.z, n = blockIdx.x;
    for (int i = tid; i < 2 * HH * 64; i += 192) {
        int t = i / (HH * 64), r = i % (HH * 64);
        su[t][r / 64][r % 64] = d_u[t][r / 64][half * 64 + (r % 64)];
    }
    __syncthreads();

    int s = tid;
    float as[HH] = {0.f, 0.f, 0.f, 0.f};
    float ad[HH] = {0.f, 0.f, 0.f, 0.f};
    const float* Xp = X + (((size_t)b * FIN + half * 64) * NN + n) * SS + s;
    const size_t FST = (size_t)NN * SS;

    #pragma unroll
    for (int f0 = 0; f0 < 64; f0 += 32) {
        float xv[32];
        #pragma unroll
        for (int k = 0; k < 32; k++) xv[k] = Xp[(f0 + k) * FST];
        #pragma unroll
        for (int k = 0; k < 32; k++) {
            float x = xv[k];
            #pragma unroll
            for (int h = 0; h < HH; h++) {
                as[h] += x * su[0][h][f0 + k];
                ad[h] += x * su[1][h][f0 + k];
            }
        }
    }
    float cb = b_attn[0];
    #pragma unroll
    for (int h = 0; h < HH; h++) {
        float cs = (half == 0) ? (d_c[0][h] + cb) : 0.f;
        float cd = (half == 0) ? d_c[1][h] : 0.f;
        d_SsrcP[half][b][h][n][s] = (as[h] + cs) * L2E;
        d_SdstP[half][b][h][n][s] = (ad[h] + cd) * L2E;
    }
}

// ---------------- K2: X row sums (X in L2 after k_proj) ----------------
__global__ void k_sumx(const float* __restrict__ X) {
    int bf = blockIdx.x;  // 256 blocks
    const float4* p = (const float4*)(X + (size_t)bf * (NN * SS));
    float acc = 0.f;
    for (int i = threadIdx.x; i < NN * SS / 4; i += 256) {
        float4 v = p[i];
        acc += (v.x + v.y) + (v.z + v.w);
    }
    __shared__ float sm[256];
    sm[threadIdx.x] = acc;
    __syncthreads();
    #pragma unroll
    for (int st = 128; st > 0; st >>= 1) {
        if (threadIdx.x < st) sm[threadIdx.x] += sm[threadIdx.x + st];
        __syncthreads();
    }
    if (threadIdx.x == 0) d_sumx[bf] = sm[0];
}

// ---------------- K3: fused attention + sum_g + output ----------------
// grid (16, HH, BB) = 128 blocks, block 960.
__global__ void __launch_bounds__(TPA) k_attn(const int* __restrict__ A,
                                              const float* __restrict__ W_lin,
                                              const float* __restrict__ b_lin,
                                              float* __restrict__ out) {
    extern __shared__ float smem[];
    __half*  slabh = (__half*)(smem + W_SLAB);   // pitch 194 halves per s row
    __half2* slab2 = (__half2*)(smem + W_SLAB);  // pitch 97
    __half2* Eh2   = (__half2*)(smem + W_EH);    // pitch 97
    float*   ssv   = smem + W_SSV;
    float*   rden  = smem + W_RDEN;
    float*   part  = smem + W_PART;
    float*   aph   = smem + W_APH;
    float*   sgs   = smem + W_SGS;

    int tid = threadIdx.x;
    int h = blockIdx.y, b = blockIdx.z;
    int nbase = blockIdx.x * CH;

    // ---- prologue A: slab staging (fp16 transpose), A bits, ssv(n0), sum_g partials
    int mkbits = 0;
    {
        const float4* p0 = (const float4*)&d_SdstP[0][b][h][0][0];
        const float4* p1 = (const float4*)&d_SdstP[1][b][h][0][0];
        #pragma unroll
        for (int i = tid; i < NN * SS / 4; i += TPA) {
            float4 v0 = p0[i], v1 = p1[i];
            int e = i * 4;
            int m = e / SS, s = e % SS;
            slabh[(s    ) * 194 + m] = __float2half(v0.x + v1.x);
            slabh[(s + 1) * 194 + m] = __float2half(v0.y + v1.y);
            slabh[(s + 2) * 194 + m] = __float2half(v0.z + v1.z);
            slabh[(s + 3) * 194 + m] = __float2half(v0.w + v1.w);
        }
    }
    if (tid < SS) {
        const int4* ap = (const int4*)(A + tid * NN + nbase);
        #pragma unroll
        for (int q = 0; q < 3; q++) {
            int4 a4 = ap[q];
            mkbits |= (a4.x != 0) << (q * 4);
            mkbits |= (a4.y != 0) << (q * 4 + 1);
            mkbits |= (a4.z != 0) << (q * 4 + 2);
            mkbits |= (a4.w != 0) << (q * 4 + 3);
        }
        float v = d_SsrcP[0][b][h][nbase][tid] + d_SsrcP[1][b][h][nbase][tid];
        ssv[tid] = (mkbits & 1) ? v : -1e30f;
    }
    if (tid >= 256 && tid < 768) {
        int t = tid - 256, d = t >> 3, k = t & 7;
        float acc = 0.f;
        const float* wp = W_lin + h * 64 + d;
        #pragma unroll
        for (int f = k * 16; f < k * 16 + 16; f++)
            acc += (d_sumx[f] + d_sumx[FIN + f]) * wp[f * CC];
        part[tid] = acc;
    }
    __syncthreads();
    if (tid >= 256 && tid < 320) {
        int d = tid - 256;
        float s = 0.f;
        #pragma unroll
        for (int k = 0; k < 8; k++) s += part[256 + d * 8 + k];
        sgs[d] = s + TOTF * b_lin[h * 64 + d];
    }
    __syncthreads();

    int ii2 = tid % 96, jj = tid / 96;      // pass1: m-pair, s-chunk (10)
    int s0 = (jj * SS) / 10, s1 = ((jj + 1) * SS) / 10;
    int ii = tid % 192, jj5 = tid / 192;    // pass2: s, m-pair-chunk (5)
    int p0i = (jj5 * 96) / 5, p1i = ((jj5 + 1) * 96) / 5;

    for (int ni = 0; ni < CH; ni++) {
        int n = nbase + ni;

        // pass 1: E (fp16x2) + denom partials. thread = (m-pair ii2, s-chunk jj)
        {
            float a0 = 0.f, a1 = 0.f;
            #pragma unroll 4
            for (int s = s0; s < s1; s++) {
                __half2 d2 = slab2[s * EPH + ii2];
                float2 dv = __half22float2(d2);
                float sv = ssv[s];
                float t0 = sv + dv.x, t1 = sv + dv.y;
                t0 = fmaxf(t0, NEG * t0);
                t1 = fmaxf(t1, NEG * t1);
                __half2 th = __floats2half2_rn(t0, t1);
                unsigned eu = h2ex2u(*reinterpret_cast<unsigned*>(&th));
                Eh2[s * EPH + ii2] = *reinterpret_cast<__half2*>(&eu);
                float2 ef = __half22float2(*reinterpret_cast<__half2*>(&eu));
                a0 += ef.x; a1 += ef.y;
            }
            ((float2*)part)[jj * 96 + ii2] = make_float2(a0, a1);
        }
        __syncthreads();
        if (tid < NN) {
            float s = 0.f;
            #pragma unroll
            for (int q = 0; q < 10; q++) s += part[q * 192 + tid];
            rden[tid] = __fdividef(1.f, s);
        }
        __syncthreads();

        // pass 2: alpha row-sums. thread = (s=ii, m-pair chunk jj5)
        {
            const __half2* er = Eh2 + ii * EPH;
            const float2* rd2 = (const float2*)rden;
            float a0 = 0.f, a1 = 0.f;
            #pragma unroll 4
            for (int p = p0i; p < p1i; p++) {
                float2 e = __half22float2(er[p]);
                float2 r = rd2[p];
                a0 += e.x * r.x;
                a1 += e.y * r.y;
            }
            part[jj5 * 192 + ii] = a0 + a1;
        }
        __syncthreads();
        if (tid < SS) {
            aph[tid] = part[tid] + part[192 + tid] + part[384 + tid]
                     + part[576 + tid] + part[768 + tid];
            if (ni + 1 < CH) {
                float v = d_SsrcP[0][b][h][n + 1][tid] + d_SsrcP[1][b][h][n + 1][tid];
                ssv[tid] = ((mkbits >> (ni + 1)) & 1) ? v : -1e30f;
            }
        }
        __syncthreads();

        // output: out[b, h*64+d, n, s] = aph[s] * sgs[d]
        {
            float4* outp = (float4*)out;
            size_t cb0 = (size_t)b * CC + h * 64;
            #pragma unroll
            for (int idx = tid; idx < 64 * 48; idx += TPA) {
                int d = idx / 48, s4 = idx - d * 48;
                float g = sgs[d];
                float4 a = ((const float4*)aph)[s4];
                outp[((cb0 + d) * NN + n) * 48 + s4] =
                    make_float4(a.x * g, a.y * g, a.z * g, a.w * g);
            }
        }
    }
}

extern "C" void kernel_launch(void* const* d_in, const int* in_sizes, int n_in,
                              void* d_out, int out_size) {
    const float* X      = (const float*)d_in[0];
    const int*   A      = (const int*)  d_in[1];
    const float* W_lin  = (const float*)d_in[2];
    const float* b_lin  = (const float*)d_in[3];
    const float* W_attn = (const float*)d_in[4];
    const float* b_attn = (const float*)d_in[5];
    float* out = (float*)d_out;

    const int SMEM_ATTN = W_TOT * 4;  // 159232 B
    cudaFuncSetAttribute(k_attn, cudaFuncAttributeMaxDynamicSharedMemorySize, SMEM_ATTN);

    k_prep<<<1, 128>>>(W_lin, b_lin, W_attn);
    k_proj<<<dim3(NN, 2, BB), 192>>>(X, b_attn);
    k_sumx<<<BB * FIN, 256>>>(X);
    k_attn<<<dim3(NN / CH, HH, BB), TPA, SMEM_ATTN>>>(A, W_lin, b_lin, out);
}

// round 7
// speedup vs baseline: 1.7314x; 1.0946x over previous
#include <cuda_runtime.h>
#include <cuda_fp16.h>

#define BB 2
#define FIN 128
#define NN 192
#define SS 192
#define HH 4
#define DD 64
#define CC 256          // H*D
#define NEG 0.2f
#define TOTF 73728.0f   // B*S*N
#define L2E 1.44269504088896f
#define CH 12           // n per attn block -> 16*4*2 = 128 blocks (1 wave)
#define NB 6            // n per sub-batch
#define TPA 960
#define EPH 97          // half2 pitch (words) for slab: odd -> conflict-free

// smem word offsets
#define W_SLAB 0        // half2 [192 s][97 pairs]
#define W_SSV  18624    // half2 [12 n][192 s] (broadcast pairs; masked = -inf)
#define W_PART 20928    // 11520 f32: pass1 [10][6][96] float2 / pass2 [5][6][192]
#define W_RDEN 32448    // [6][192] f32
#define W_APH  33600    // [6][192] f32 (also sum_g temp in prologue)
#define W_SGS  34752    // 64 f32
#define W_TOT  34816    // 139264 bytes

__device__ __forceinline__ __half2 h2ex2(__half2 x) {
    unsigned r, xi = *reinterpret_cast<unsigned*>(&x);
    asm("ex2.approx.f16x2 %0, %1;" : "=r"(r) : "r"(xi));
    return *reinterpret_cast<__half2*>(&r);
}

// ---------------- scratch ----------------
__device__ float d_u[2][HH][FIN];
__device__ float d_c[2][HH];
__device__ float d_sumx[BB * FIN];
__device__ float d_SsrcP[2][BB][HH][NN][SS];  // f-half partials, pre-scaled log2e
__device__ float d_SdstP[2][BB][HH][NN][SS];

// ---------------- K0: u vectors + bias constants ----------------
__global__ void k_prep(const float* __restrict__ W_lin,
                       const float* __restrict__ b_lin,
                       const float* __restrict__ W_attn) {
    int f = threadIdx.x;  // 128
    #pragma unroll
    for (int h = 0; h < HH; h++) {
        float as = 0.f, ad = 0.f;
        #pragma unroll 8
        for (int d = 0; d < DD; d++) {
            float w = W_lin[f * CC + h * DD + d];
            as += w * W_attn[d];
            ad += w * W_attn[DD + d];
        }
        d_u[0][h][f] = as;
        d_u[1][h][f] = ad;
    }
    if (f < HH) {
        int h = f;
        float cs = 0.f, cd = 0.f;
        for (int d = 0; d < DD; d++) {
            cs += b_lin[h * DD + d] * W_attn[d];
            cd += b_lin[h * DD + d] * W_attn[DD + d];
        }
        d_c[0][h] = cs;
        d_c[1][h] = cd;
    }
}

// ---------------- K1: projections, f split in 2 halves ----------------
// grid (192, 2, BB), block 192 (=s)
__global__ void __launch_bounds__(192) k_proj(const float* __restrict__ X,
                                              const float* __restrict__ b_attn) {
    __shared__ float su[2][HH][64];
    int tid = threadIdx.x;
    int half = blockIdx.y, b = blockIdx.z, n = blockIdx.x;
    for (int i = tid; i < 2 * HH * 64; i += 192) {
        int t = i / (HH * 64), r = i % (HH * 64);
        su[t][r / 64][r % 64] = d_u[t][r / 64][half * 64 + (r % 64)];
    }
    __syncthreads();

    int s = tid;
    float as[HH] = {0.f, 0.f, 0.f, 0.f};
    float ad[HH] = {0.f, 0.f, 0.f, 0.f};
    const float* Xp = X + (((size_t)b * FIN + half * 64) * NN + n) * SS + s;
    const size_t FST = (size_t)NN * SS;

    #pragma unroll
    for (int f0 = 0; f0 < 64; f0 += 32) {
        float xv[32];
        #pragma unroll
        for (int k = 0; k < 32; k++) xv[k] = Xp[(f0 + k) * FST];
        #pragma unroll
        for (int k = 0; k < 32; k++) {
            float x = xv[k];
            #pragma unroll
            for (int h = 0; h < HH; h++) {
                as[h] += x * su[0][h][f0 + k];
                ad[h] += x * su[1][h][f0 + k];
            }
        }
    }
    float cb = b_attn[0];
    #pragma unroll
    for (int h = 0; h < HH; h++) {
        float cs = (half == 0) ? (d_c[0][h] + cb) : 0.f;
        float cd = (half == 0) ? d_c[1][h] : 0.f;
        d_SsrcP[half][b][h][n][s] = (as[h] + cs) * L2E;
        d_SdstP[half][b][h][n][s] = (ad[h] + cd) * L2E;
    }
}

// ---------------- K2: X row sums (X in L2 after k_proj) ----------------
__global__ void k_sumx(const float* __restrict__ X) {
    int bf = blockIdx.x;  // 256 blocks
    const float4* p = (const float4*)(X + (size_t)bf * (NN * SS));
    float acc = 0.f;
    for (int i = threadIdx.x; i < NN * SS / 4; i += 256) {
        float4 v = p[i];
        acc += (v.x + v.y) + (v.z + v.w);
    }
    __shared__ float sm[256];
    sm[threadIdx.x] = acc;
    __syncthreads();
    #pragma unroll
    for (int st = 128; st > 0; st >>= 1) {
        if (threadIdx.x < st) sm[threadIdx.x] += sm[threadIdx.x + st];
        __syncthreads();
    }
    if (threadIdx.x == 0) d_sumx[bf] = sm[0];
}

// ---------------- K3: fused attention + sum_g + output ----------------
// grid (16, HH, BB) = 128 blocks, block 960. n batched 2x6, E recomputed.
__global__ void __launch_bounds__(TPA) k_attn(const int* __restrict__ A,
                                              const float* __restrict__ W_lin,
                                              const float* __restrict__ b_lin,
                                              float* __restrict__ out) {
    extern __shared__ float smem[];
    __half*  slabh = (__half*)(smem + W_SLAB);   // [s][194 halves]
    __half2* slab2 = (__half2*)(smem + W_SLAB);  // [s][EPH pairs]
    __half2* ssv2  = (__half2*)(smem + W_SSV);   // [12][192]
    float*   part  = smem + W_PART;
    float*   rden  = smem + W_RDEN;
    float*   aph   = smem + W_APH;
    float*   sgs   = smem + W_SGS;

    int tid = threadIdx.x;
    int h = blockIdx.y, b = blockIdx.z;
    int nbase = blockIdx.x * CH;
    const __half2 neg2 = __float2half2_rn(NEG);

    // ---- prologue: slab (fp16 transpose), ssv2 (mask folded), sum_g ----
    {
        const float4* p0 = (const float4*)&d_SdstP[0][b][h][0][0];
        const float4* p1 = (const float4*)&d_SdstP[1][b][h][0][0];
        #pragma unroll
        for (int i = tid; i < NN * SS / 4; i += TPA) {
            float4 v0 = p0[i], v1 = p1[i];
            int e = i * 4;
            int m = e / SS, s = e % SS;
            slabh[(s    ) * 194 + m] = __float2half(v0.x + v1.x);
            slabh[(s + 1) * 194 + m] = __float2half(v0.y + v1.y);
            slabh[(s + 2) * 194 + m] = __float2half(v0.z + v1.z);
            slabh[(s + 3) * 194 + m] = __float2half(v0.w + v1.w);
        }
    }
    for (int i = tid; i < CH * SS; i += TPA) {
        int n = i / SS, s = i - n * SS;
        float v = d_SsrcP[0][b][h][nbase + n][s] + d_SsrcP[1][b][h][nbase + n][s];
        v = (A[s * NN + nbase + n] != 0) ? v : -1e6f;  // -1e6 -> -inf in half
        ssv2[i] = __float2half2_rn(v);
    }
    if (tid >= 256 && tid < 768) {  // sum_g partials into aph temp
        int t = tid - 256, d = t >> 3, k = t & 7;
        float acc = 0.f;
        const float* wp = W_lin + h * 64 + d;
        #pragma unroll
        for (int f = k * 16; f < k * 16 + 16; f++)
            acc += (d_sumx[f] + d_sumx[FIN + f]) * wp[f * CC];
        aph[t] = acc;
    }
    __syncthreads();
    if (tid >= 256 && tid < 320) {
        int d = tid - 256;
        float s = 0.f;
        #pragma unroll
        for (int k = 0; k < 8; k++) s += aph[d * 8 + k];
        sgs[d] = s + TOTF * b_lin[h * 64 + d];
    }
    __syncthreads();

    int p1idx = tid % 96, jj = tid / 96;              // pass1: pair, s-chunk(10)
    int s0 = (jj * SS) / 10, s1 = ((jj + 1) * SS) / 10;
    int sI = tid % 192, jj5 = tid / 192;              // pass2: s, pair-chunk(5)
    int q0 = (jj5 * 96) / 5, q1 = ((jj5 + 1) * 96) / 5;

    #pragma unroll
    for (int batch = 0; batch < CH / NB; batch++) {
        const __half2* sv_base = ssv2 + batch * NB * SS;

        // pass 1: denom partials for 6 n per slab load
        {
            float2 acc[NB];
            #pragma unroll
            for (int n = 0; n < NB; n++) acc[n] = make_float2(0.f, 0.f);
            #pragma unroll 2
            for (int s = s0; s < s1; s++) {
                __half2 d2 = slab2[s * EPH + p1idx];
                #pragma unroll
                for (int n = 0; n < NB; n++) {
                    __half2 t = __hadd2(sv_base[n * SS + s], d2);
                    t = __hmax2(t, __hmul2(t, neg2));
                    float2 ef = __half22float2(h2ex2(t));
                    acc[n].x += ef.x; acc[n].y += ef.y;
                }
            }
            #pragma unroll
            for (int n = 0; n < NB; n++)
                ((float2*)part)[(jj * NB + n) * 96 + p1idx] = acc[n];
        }
        __syncthreads();
        for (int i = tid; i < NB * NN; i += TPA) {
            float s = 0.f;
            #pragma unroll
            for (int q = 0; q < 10; q++) s += part[q * NB * NN + i];
            rden[i] = (s > 0.f) ? __fdividef(1.f, s) : 0.f;
        }
        __syncthreads();

        // pass 2: recompute E, alpha accumulation for 6 n per slab load
        {
            __half2 sv[NB];
            #pragma unroll
            for (int n = 0; n < NB; n++) sv[n] = sv_base[n * SS + sI];
            float acc[NB];
            #pragma unroll
            for (int n = 0; n < NB; n++) acc[n] = 0.f;
            #pragma unroll 2
            for (int q = q0; q < q1; q++) {
                __half2 d2 = slab2[sI * EPH + q];
                #pragma unroll
                for (int n = 0; n < NB; n++) {
                    __half2 t = __hadd2(sv[n], d2);
                    t = __hmax2(t, __hmul2(t, neg2));
                    float2 ef = __half22float2(h2ex2(t));
                    float2 r = ((const float2*)(rden + n * NN))[q];
                    acc[n] += ef.x * r.x + ef.y * r.y;
                }
            }
            #pragma unroll
            for (int n = 0; n < NB; n++)
                part[(jj5 * NB + n) * NN + sI] = acc[n];
        }
        __syncthreads();
        for (int i = tid; i < NB * NN; i += TPA) {
            aph[i] = part[i] + part[NB * NN + i] + part[2 * NB * NN + i]
                   + part[3 * NB * NN + i] + part[4 * NB * NN + i];
        }
        __syncthreads();

        // output: out[b, h*64+d, ng, s] = aph[n][s] * sgs[d]
        {
            float4* outp = (float4*)out;
            size_t cb0 = (size_t)b * CC + h * 64;
            #pragma unroll
            for (int idx = tid; idx < NB * 64 * 48; idx += TPA) {
                int n = idx / 3072, r = idx - n * 3072;
                int d = r / 48, s4 = r - d * 48;
                float g = sgs[d];
                float4 a = ((const float4*)(aph + n * NN))[s4];
                int ng = nbase + batch * NB + n;
                outp[((cb0 + d) * NN + ng) * 48 + s4] =
                    make_float4(a.x * g, a.y * g, a.z * g, a.w * g);
            }
        }
        __syncthreads();
    }
}

extern "C" void kernel_launch(void* const* d_in, const int* in_sizes, int n_in,
                              void* d_out, int out_size) {
    const float* X      = (const float*)d_in[0];
    const int*   A      = (const int*)  d_in[1];
    const float* W_lin  = (const float*)d_in[2];
    const float* b_lin  = (const float*)d_in[3];
    const float* W_attn = (const float*)d_in[4];
    const float* b_attn = (const float*)d_in[5];
    float* out = (float*)d_out;

    const int SMEM_ATTN = W_TOT * 4;  // 139264 B
    cudaFuncSetAttribute(k_attn, cudaFuncAttributeMaxDynamicSharedMemorySize, SMEM_ATTN);

    k_prep<<<1, 128>>>(W_lin, b_lin, W_attn);
    k_proj<<<dim3(NN, 2, BB), 192>>>(X, b_attn);
    k_sumx<<<BB * FIN, 256>>>(X);
    k_attn<<<dim3(NN / CH, HH, BB), TPA, SMEM_ATTN>>>(A, W_lin, b_lin, out);
}

// round 8
// speedup vs baseline: 1.7334x; 1.0011x over previous
#include <cuda_runtime.h>
#include <cuda_fp16.h>

#define BB 2
#define FIN 128
#define NN 192
#define SS 192
#define HH 4
#define DD 64
#define CC 256          // H*D
#define NEG 0.2f
#define TOTF 73728.0f   // B*S*N
#define L2E 1.44269504088896f
#define CH 6            // n per attn block -> 32*4*2 = 256 blocks
#define TPA 576
#define EPH 97          // half2 pitch for slab rows (odd -> conflict-free)

// smem word offsets (fp32 words)
#define W_SLAB 0        // half2 [192 s][97 pairs]           18624
#define W_SSV  18624    // half2 [6 n][192 s]                 1152
#define W_PART 19776    // pass1 float2[6][96] / pass2 f32[3][192]  1152
#define W_RDEN 20928    // float2 [96]                         192
#define W_APH  21120    // f32 [192] (16B aligned)             192
#define W_SGS  21312    // f32 [64]                             64
#define W_SL   21376    // uchar [6][192]                      288
#define W_SLOT 21664    // uchar [6][192]                      288
#define W_CNT  21952    // int cnt[6] + wcnt[36]                44
#define W_TOT  21996    // 87984 bytes -> 2 blocks/SM

__device__ __forceinline__ __half2 h2ex2(__half2 x) {
    unsigned r, xi = *reinterpret_cast<unsigned*>(&x);
    asm("ex2.approx.f16x2 %0, %1;" : "=r"(r) : "r"(xi));
    return *reinterpret_cast<__half2*>(&r);
}

// ---------------- scratch ----------------
__device__ float d_u[2][HH][FIN];
__device__ float d_c[2][HH];
__device__ float d_sumx[BB * FIN];
__device__ float d_SsrcP[2][BB][HH][NN][SS];  // f-half partials, pre-scaled log2e
__device__ float d_SdstP[2][BB][HH][NN][SS];

// ---------------- K0: u vectors + bias constants ----------------
__global__ void k_prep(const float* __restrict__ W_lin,
                       const float* __restrict__ b_lin,
                       const float* __restrict__ W_attn) {
    int f = threadIdx.x;  // 128
    #pragma unroll
    for (int h = 0; h < HH; h++) {
        float as = 0.f, ad = 0.f;
        #pragma unroll 8
        for (int d = 0; d < DD; d++) {
            float w = W_lin[f * CC + h * DD + d];
            as += w * W_attn[d];
            ad += w * W_attn[DD + d];
        }
        d_u[0][h][f] = as;
        d_u[1][h][f] = ad;
    }
    if (f < HH) {
        int h = f;
        float cs = 0.f, cd = 0.f;
        for (int d = 0; d < DD; d++) {
            cs += b_lin[h * DD + d] * W_attn[d];
            cd += b_lin[h * DD + d] * W_attn[DD + d];
        }
        d_c[0][h] = cs;
        d_c[1][h] = cd;
    }
}

// ---------------- K1: projections, f split in 2 halves ----------------
__global__ void __launch_bounds__(192) k_proj(const float* __restrict__ X,
                                              const float* __restrict__ b_attn) {
    __shared__ float su[2][HH][64];
    int tid = threadIdx.x;
    int half = blockIdx.y, b = blockIdx.z, n = blockIdx.x;
    for (int i = tid; i < 2 * HH * 64; i += 192) {
        int t = i / (HH * 64), r = i % (HH * 64);
        su[t][r / 64][r % 64] = d_u[t][r / 64][half * 64 + (r % 64)];
    }
    __syncthreads();

    int s = tid;
    float as[HH] = {0.f, 0.f, 0.f, 0.f};
    float ad[HH] = {0.f, 0.f, 0.f, 0.f};
    const float* Xp = X + (((size_t)b * FIN + half * 64) * NN + n) * SS + s;
    const size_t FST = (size_t)NN * SS;

    #pragma unroll
    for (int f0 = 0; f0 < 64; f0 += 32) {
        float xv[32];
        #pragma unroll
        for (int k = 0; k < 32; k++) xv[k] = Xp[(f0 + k) * FST];
        #pragma unroll
        for (int k = 0; k < 32; k++) {
            float x = xv[k];
            #pragma unroll
            for (int h = 0; h < HH; h++) {
                as[h] += x * su[0][h][f0 + k];
                ad[h] += x * su[1][h][f0 + k];
            }
        }
    }
    float cb = b_attn[0];
    #pragma unroll
    for (int h = 0; h < HH; h++) {
        float cs = (half == 0) ? (d_c[0][h] + cb) : 0.f;
        float cd = (half == 0) ? d_c[1][h] : 0.f;
        d_SsrcP[half][b][h][n][s] = (as[h] + cs) * L2E;
        d_SdstP[half][b][h][n][s] = (ad[h] + cd) * L2E;
    }
}

// ---------------- K2: X row sums ----------------
__global__ void k_sumx(const float* __restrict__ X) {
    int bf = blockIdx.x;  // 256 blocks
    const float4* p = (const float4*)(X + (size_t)bf * (NN * SS));
    float acc = 0.f;
    for (int i = threadIdx.x; i < NN * SS / 4; i += 256) {
        float4 v = p[i];
        acc += (v.x + v.y) + (v.z + v.w);
    }
    __shared__ float sm[256];
    sm[threadIdx.x] = acc;
    __syncthreads();
    #pragma unroll
    for (int st = 128; st > 0; st >>= 1) {
        if (threadIdx.x < st) sm[threadIdx.x] += sm[threadIdx.x + st];
        __syncthreads();
    }
    if (threadIdx.x == 0) d_sumx[bf] = sm[0];
}

// ---------------- K3: fused attention + sum_g + output ----------------
// grid (32, HH, BB) = 256 blocks, block 576, 2 blocks/SM.
__global__ void __launch_bounds__(TPA, 2) k_attn(const int* __restrict__ A,
                                                 const float* __restrict__ W_lin,
                                                 const float* __restrict__ b_lin,
                                                 float* __restrict__ out) {
    extern __shared__ float smem[];
    __half*        slabh = (__half*)(smem + W_SLAB);   // [s][194 halves]
    __half2*       slab2 = (__half2*)(smem + W_SLAB);  // [s][EPH]
    __half2*       ssv2  = (__half2*)(smem + W_SSV);   // [6][192]
    float*         part  = smem + W_PART;
    float2*        part2 = (float2*)part;
    float2*        rden2 = (float2*)(smem + W_RDEN);
    float*         aph   = smem + W_APH;
    float*         sgs   = smem + W_SGS;
    unsigned char* slist = (unsigned char*)(smem + W_SL);
    unsigned char* slot  = (unsigned char*)(smem + W_SLOT);
    int*           cnt   = (int*)(smem + W_CNT);
    int*           wcnt  = cnt + 6;

    int tid = threadIdx.x;
    int h = blockIdx.y, b = blockIdx.z;
    int nbase = blockIdx.x * CH;
    const __half2 neg2 = __float2half2_rn(NEG);

    // ---- prologue A: slab (fp16 transpose), ssv, mask ballots, sum_g partials
    {
        const float4* p0 = (const float4*)&d_SdstP[0][b][h][0][0];
        const float4* p1 = (const float4*)&d_SdstP[1][b][h][0][0];
        #pragma unroll
        for (int i = tid; i < NN * SS / 4; i += TPA) {
            float4 v0 = p0[i], v1 = p1[i];
            int e = i * 4;
            int m = e / SS, s = e % SS;
            slabh[(s    ) * 194 + m] = __float2half(v0.x + v1.x);
            slabh[(s + 1) * 194 + m] = __float2half(v0.y + v1.y);
            slabh[(s + 2) * 194 + m] = __float2half(v0.z + v1.z);
            slabh[(s + 3) * 194 + m] = __float2half(v0.w + v1.w);
        }
    }
    #pragma unroll
    for (int i = tid; i < CH * SS; i += TPA) {
        int n = i / SS, s = i - n * SS;
        float v = d_SsrcP[0][b][h][nbase + n][s] + d_SsrcP[1][b][h][nbase + n][s];
        ssv2[i] = __float2half2_rn(v);
    }
    unsigned bals[CH];
    int mkbits = 0;
    if (tid < SS) {
        #pragma unroll
        for (int ni = 0; ni < CH; ni++) {
            int mk = (A[tid * NN + nbase + ni] != 0);
            unsigned bal = __ballot_sync(0xFFFFFFFFu, mk);
            bals[ni] = bal;
            mkbits |= mk << ni;
            if ((tid & 31) == 0) wcnt[ni * 6 + (tid >> 5)] = __popc(bal);
        }
    }
    if (tid >= 64) {  // 512 threads: sum_g partials into part temp
        int t = tid - 64, d = t >> 3, k = t & 7;
        float acc = 0.f;
        const float* wp = W_lin + h * 64 + d;
        #pragma unroll
        for (int f = k * 16; f < k * 16 + 16; f++)
            acc += (d_sumx[f] + d_sumx[FIN + f]) * wp[f * CC];
        part[t] = acc;
    }
    __syncthreads();

    // ---- prologue B: lists + slots + counts + sgs
    if (tid < SS) {
        int w = tid >> 5, l = tid & 31;
        unsigned lmask = (1u << l) - 1u;
        #pragma unroll
        for (int ni = 0; ni < CH; ni++) {
            if ((mkbits >> ni) & 1) {
                int base = 0;
                #pragma unroll
                for (int q = 0; q < 5; q++) base += (q < w) ? wcnt[ni * 6 + q] : 0;
                int pos = base + __popc(bals[ni] & lmask);
                slist[ni * 192 + pos] = (unsigned char)tid;
                slot[ni * 192 + tid] = (unsigned char)pos;
            } else {
                slot[ni * 192 + tid] = 255;
            }
        }
    }
    if (tid >= 192 && tid < 192 + CH) {
        int ni = tid - 192;
        cnt[ni] = wcnt[ni * 6] + wcnt[ni * 6 + 1] + wcnt[ni * 6 + 2]
                + wcnt[ni * 6 + 3] + wcnt[ni * 6 + 4] + wcnt[ni * 6 + 5];
    }
    __syncthreads();
    if (tid >= 256 && tid < 320) {
        int d = tid - 256;
        float s = 0.f;
        #pragma unroll
        for (int k = 0; k < 8; k++) s += part[d * 8 + k];
        sgs[d] = s + TOTF * b_lin[h * 64 + d];
    }
    __syncthreads();

    int p1p = tid % 96, jj = tid / 96;     // pass1: m-pair, s-chunk (6)
    int sI = tid % 192, jj3 = tid / 192;   // pass2: slot, m-pair-chunk (3)
    size_t cb0 = (size_t)b * CC + h * 64;
    float4* outp = (float4*)out;

    for (int ni = 0; ni < CH; ni++) {
        int c = cnt[ni];
        const unsigned char* sl = slist + ni * 192;
        const __half2* svn = ssv2 + ni * SS;

        // pass 1: denom partials over compacted s. thread = (pair, chunk)
        {
            int i0 = (c * jj) / 6, i1 = (c * (jj + 1)) / 6;
            float a0 = 0.f, a1 = 0.f;
            for (int i = i0; i < i1; i++) {
                int s = sl[i];
                __half2 t = __hadd2(svn[s], slab2[s * EPH + p1p]);
                t = __hmax2(t, __hmul2(t, neg2));
                float2 ef = __half22float2(h2ex2(t));
                a0 += ef.x; a1 += ef.y;
            }
            part2[jj * 96 + p1p] = make_float2(a0, a1);
        }
        __syncthreads();
        if (tid < 96) {
            float dx = 0.f, dy = 0.f;
            #pragma unroll
            for (int q = 0; q < 6; q++) {
                float2 v = part2[q * 96 + tid];
                dx += v.x; dy += v.y;
            }
            rden2[tid] = make_float2(dx > 0.f ? __fdividef(1.f, dx) : 0.f,
                                     dy > 0.f ? __fdividef(1.f, dy) : 0.f);
        }
        // overlap: write output of previous n while rden reduces
        if (ni > 0) {
            int nOut = nbase + ni - 1;
            #pragma unroll
            for (int idx = tid; idx < 64 * 48; idx += TPA) {
                int d = idx / 48, s4 = idx - d * 48;
                float g = sgs[d];
                float4 a = ((const float4*)aph)[s4];
                outp[((cb0 + d) * NN + nOut) * 48 + s4] =
                    make_float4(a.x * g, a.y * g, a.z * g, a.w * g);
            }
        }
        __syncthreads();

        // pass 2: alpha partials. thread = (compact slot sI, pair-chunk jj3)
        if (sI < c) {
            int s = sl[sI];
            __half2 sv = svn[s];
            const __half2* row = slab2 + s * EPH;
            float a = 0.f;
            #pragma unroll 4
            for (int q = jj3 * 32; q < jj3 * 32 + 32; q++) {
                __half2 t = __hadd2(sv, row[q]);
                t = __hmax2(t, __hmul2(t, neg2));
                float2 ef = __half22float2(h2ex2(t));
                float2 r = rden2[q];
                a += ef.x * r.x + ef.y * r.y;
            }
            part[jj3 * 192 + sI] = a;
        }
        __syncthreads();
        if (tid < SS) {
            int k = slot[ni * 192 + tid];
            aph[tid] = (k != 255)
                ? part[k] + part[192 + k] + part[384 + k] : 0.f;
        }
        __syncthreads();
    }
    // final output (n = nbase + CH - 1)
    {
        int nOut = nbase + CH - 1;
        #pragma unroll
        for (int idx = tid; idx < 64 * 48; idx += TPA) {
            int d = idx / 48, s4 = idx - d * 48;
            float g = sgs[d];
            float4 a = ((const float4*)aph)[s4];
            outp[((cb0 + d) * NN + nOut) * 48 + s4] =
                make_float4(a.x * g, a.y * g, a.z * g, a.w * g);
        }
    }
}

extern "C" void kernel_launch(void* const* d_in, const int* in_sizes, int n_in,
                              void* d_out, int out_size) {
    const float* X      = (const float*)d_in[0];
    const int*   A      = (const int*)  d_in[1];
    const float* W_lin  = (const float*)d_in[2];
    const float* b_lin  = (const float*)d_in[3];
    const float* W_attn = (const float*)d_in[4];
    const float* b_attn = (const float*)d_in[5];
    float* out = (float*)d_out;

    const int SMEM_ATTN = W_TOT * 4;  // 87984 B
    cudaFuncSetAttribute(k_attn, cudaFuncAttributeMaxDynamicSharedMemorySize, SMEM_ATTN);

    k_prep<<<1, 128>>>(W_lin, b_lin, W_attn);
    k_proj<<<dim3(NN, 2, BB), 192>>>(X, b_attn);
    k_sumx<<<BB * FIN, 256>>>(X);
    k_attn<<<dim3(NN / CH, HH, BB), TPA, SMEM_ATTN>>>(A, W_lin, b_lin, out);
}